// round 1
// baseline (speedup 1.0000x reference)
#include <cuda_runtime.h>
#include <math.h>

#define B_  64
#define T_  20
#define H_  512
#define E_  512
#define V_  32000
#define NN_ 8192
#define G4  2048   // 4*H

// ---------------- static scratch (no allocations allowed) ----------------
__device__ float d_node_proj[NN_ * H_];        // [N,H]
__device__ float d_embpart[T_ * B_ * G4];      // emb @ Wih0_E^T + b_ih0 + b_hh0
__device__ float d_hist[B_ * T_ * H_];         // h1 history, row = b*T+t
__device__ float d_x0[B_ * 1024];              // [ctx | h0]
__device__ float d_x1[B_ * 1024];              // [h0n | h1]
__device__ float d_c0[B_ * H_];
__device__ float d_c1[B_ * H_];
__device__ float d_hp[B_ * H_];
__device__ float d_g0[B_ * G4];
__device__ float d_g1[B_ * G4];
__device__ float d_W0[G4 * 1024];              // [Wih0[:,512:] | Whh0]
__device__ float d_W1[G4 * 1024];              // [Wih1 | Whh1]
__device__ float d_bs0[G4];                    // b_ih0+b_hh0
__device__ float d_bs1[G4];                    // b_ih1+b_hh1
__device__ int   d_gidx[T_ * B_];              // caption ids, row m=t*64+b

// ---------------- generic 64x64 SGEMM, optional split-K via gridDim.z ----
// C[M,N] = A[M,K] * B[N,K]^T  (both row-major, K contiguous)
__global__ __launch_bounds__(256) void sgemm64(
    const float* __restrict__ A, int lda,
    const float* __restrict__ Bw, int ldb,
    float* __restrict__ C, int ldc,
    const float* __restrict__ Cinit,
    const float* __restrict__ bias,
    int K, const int* __restrict__ gidx)
{
    __shared__ float As[16][68];
    __shared__ float Bs[16][68];
    const int tid = threadIdx.x;
    const int m0 = blockIdx.x * 64;
    const int n0 = blockIdx.y * 64;
    const int Kc = K / gridDim.z;
    const int kbeg = blockIdx.z * Kc;
    const int kend = kbeg + Kc;

    const int ar = tid >> 2;            // 0..63
    const int ak = (tid & 3) << 2;      // 0,4,8,12
    const int arow = gidx ? gidx[m0 + ar] : (m0 + ar);
    const float* Ap = A + (size_t)arow * lda + ak;
    const float* Bp = Bw + (size_t)(n0 + ar) * ldb + ak;
    const int tx = tid & 15, ty = tid >> 4;

    float acc[4][4];
#pragma unroll
    for (int i = 0; i < 4; i++)
#pragma unroll
        for (int j = 0; j < 4; j++) acc[i][j] = 0.f;

    for (int k0 = kbeg; k0 < kend; k0 += 16) {
        float4 av = *(const float4*)(Ap + k0);
        float4 bv = *(const float4*)(Bp + k0);
        As[ak + 0][ar] = av.x; As[ak + 1][ar] = av.y;
        As[ak + 2][ar] = av.z; As[ak + 3][ar] = av.w;
        Bs[ak + 0][ar] = bv.x; Bs[ak + 1][ar] = bv.y;
        Bs[ak + 2][ar] = bv.z; Bs[ak + 3][ar] = bv.w;
        __syncthreads();
#pragma unroll
        for (int kk = 0; kk < 16; kk++) {
            float a_[4], b_[4];
            *(float4*)a_ = *(const float4*)&As[kk][ty << 2];
            *(float4*)b_ = *(const float4*)&Bs[kk][tx << 2];
#pragma unroll
            for (int i = 0; i < 4; i++)
#pragma unroll
                for (int j = 0; j < 4; j++)
                    acc[i][j] = fmaf(a_[i], b_[j], acc[i][j]);
        }
        __syncthreads();
    }

    if (gridDim.z > 1) {
#pragma unroll
        for (int i = 0; i < 4; i++) {
            int r = m0 + (ty << 2) + i;
            float* cp = C + (size_t)r * ldc + n0 + (tx << 2);
            atomicAdd(cp + 0, acc[i][0]); atomicAdd(cp + 1, acc[i][1]);
            atomicAdd(cp + 2, acc[i][2]); atomicAdd(cp + 3, acc[i][3]);
        }
    } else {
#pragma unroll
        for (int i = 0; i < 4; i++) {
            int r = m0 + (ty << 2) + i;
            int c = n0 + (tx << 2);
            float4 o = make_float4(acc[i][0], acc[i][1], acc[i][2], acc[i][3]);
            if (Cinit) {
                float4 ci = *(const float4*)(Cinit + (size_t)r * ldc + c);
                o.x += ci.x; o.y += ci.y; o.z += ci.z; o.w += ci.w;
            }
            if (bias) {
                float4 bb = *(const float4*)(bias + c);
                o.x += bb.x; o.y += bb.y; o.z += bb.z; o.w += bb.w;
            }
            *(float4*)(C + (size_t)r * ldc + c) = o;
        }
    }
}

// ---------------- 128x128 SGEMM (8x8 per thread) for the big GEMMs -------
__global__ __launch_bounds__(256) void sgemm128(
    const float* __restrict__ A, int lda,
    const float* __restrict__ Bw, int ldb,
    float* __restrict__ C, int ldc,
    const float* __restrict__ bias,
    int K, const int* __restrict__ gidx)
{
    __shared__ float As[8][132];
    __shared__ float Bs[8][132];
    const int tid = threadIdx.x;
    const int m0 = blockIdx.x * 128;
    const int n0 = blockIdx.y * 128;
    const int ar = tid >> 1;            // 0..127
    const int ak = (tid & 1) << 2;      // 0 or 4
    const int arow = gidx ? gidx[m0 + ar] : (m0 + ar);
    const float* Ap = A + (size_t)arow * lda + ak;
    const float* Bp = Bw + (size_t)(n0 + ar) * ldb + ak;
    const int tx = tid & 15, ty = tid >> 4;

    float acc[8][8];
#pragma unroll
    for (int i = 0; i < 8; i++)
#pragma unroll
        for (int j = 0; j < 8; j++) acc[i][j] = 0.f;

    for (int k0 = 0; k0 < K; k0 += 8) {
        float4 av = *(const float4*)(Ap + k0);
        float4 bv = *(const float4*)(Bp + k0);
        As[ak + 0][ar] = av.x; As[ak + 1][ar] = av.y;
        As[ak + 2][ar] = av.z; As[ak + 3][ar] = av.w;
        Bs[ak + 0][ar] = bv.x; Bs[ak + 1][ar] = bv.y;
        Bs[ak + 2][ar] = bv.z; Bs[ak + 3][ar] = bv.w;
        __syncthreads();
#pragma unroll
        for (int kk = 0; kk < 8; kk++) {
            float a_[8], b_[8];
            *(float4*)&a_[0] = *(const float4*)&As[kk][(ty << 3)];
            *(float4*)&a_[4] = *(const float4*)&As[kk][(ty << 3) + 4];
            *(float4*)&b_[0] = *(const float4*)&Bs[kk][(tx << 3)];
            *(float4*)&b_[4] = *(const float4*)&Bs[kk][(tx << 3) + 4];
#pragma unroll
            for (int i = 0; i < 8; i++)
#pragma unroll
                for (int j = 0; j < 8; j++)
                    acc[i][j] = fmaf(a_[i], b_[j], acc[i][j]);
        }
        __syncthreads();
    }

#pragma unroll
    for (int i = 0; i < 8; i++) {
        int r = m0 + (ty << 3) + i;
        int c = n0 + (tx << 3);
        float4 o0 = make_float4(acc[i][0], acc[i][1], acc[i][2], acc[i][3]);
        float4 o1 = make_float4(acc[i][4], acc[i][5], acc[i][6], acc[i][7]);
        if (bias) {
            float4 b0 = *(const float4*)(bias + c);
            float4 b1 = *(const float4*)(bias + c + 4);
            o0.x += b0.x; o0.y += b0.y; o0.z += b0.z; o0.w += b0.w;
            o1.x += b1.x; o1.y += b1.y; o1.z += b1.z; o1.w += b1.w;
        }
        *(float4*)(C + (size_t)r * ldc + c) = o0;
        *(float4*)(C + (size_t)r * ldc + c + 4) = o1;
    }
}

// ---------------- attention: segment online-softmax, ctx in registers ----
__device__ __forceinline__ int lowbound(const int* __restrict__ a, int n, int v)
{
    int lo = 0, hi = n;
    while (lo < hi) { int mid = (lo + hi) >> 1; if (a[mid] < v) lo = mid + 1; else hi = mid; }
    return lo;
}

__global__ __launch_bounds__(256) void attn_kernel(
    const int* __restrict__ batch_idx)
{
    const int b = blockIdx.x;
    __shared__ float sh_hp[512];
    __shared__ float sh_ctx[8][512];
    __shared__ float sh_m[8], sh_s[8];
    const int tid = threadIdx.x, lane = tid & 31, w = tid >> 5;

    for (int i = tid; i < 512; i += 256) sh_hp[i] = d_hp[b * 512 + i];
    __syncthreads();

    const int s0 = lowbound(batch_idx, NN_, b);
    const int s1 = lowbound(batch_idx, NN_, b + 1);

    float m = -INFINITY, ssum = 0.f;
    float ctx[16];
#pragma unroll
    for (int i = 0; i < 16; i++) ctx[i] = 0.f;

    for (int n = s0 + w; n < s1; n += 8) {
        const float* np = d_node_proj + (size_t)n * 512;
        float v[16]; float p = 0.f;
#pragma unroll
        for (int i = 0; i < 16; i++) {
            v[i] = np[lane + 32 * i];
            p = fmaf(v[i], sh_hp[lane + 32 * i], p);
        }
#pragma unroll
        for (int o = 16; o > 0; o >>= 1) p += __shfl_xor_sync(0xffffffffu, p, o);
        float mn = fmaxf(m, p);
        float scale = expf(m - mn);        // 0 when m=-inf
        float e = expf(p - mn);
        ssum = ssum * scale + e;
#pragma unroll
        for (int i = 0; i < 16; i++) ctx[i] = ctx[i] * scale + e * v[i];
        m = mn;
    }

#pragma unroll
    for (int i = 0; i < 16; i++) sh_ctx[w][lane + 32 * i] = ctx[i];
    if (lane == 0) { sh_m[w] = m; sh_s[w] = ssum; }
    __syncthreads();

    float M = -INFINITY;
#pragma unroll
    for (int ww = 0; ww < 8; ww++) M = fmaxf(M, sh_m[ww]);
    if (M == -INFINITY) {                  // empty segment (shouldn't happen)
        for (int j = tid; j < 512; j += 256) d_x0[b * 1024 + j] = 0.f;
        return;
    }
    float stot = 0.f;
    float ew[8];
#pragma unroll
    for (int ww = 0; ww < 8; ww++) { ew[ww] = expf(sh_m[ww] - M); stot += sh_s[ww] * ew[ww]; }
    float inv = 1.f / stot;
    for (int j = tid; j < 512; j += 256) {
        float num = 0.f;
#pragma unroll
        for (int ww = 0; ww < 8; ww++) num = fmaf(sh_ctx[ww][j], ew[ww], num);
        d_x0[b * 1024 + j] = num * inv;    // ctx half of x0
    }
}

// ---------------- LSTM cells + next-step gate init -----------------------
__device__ __forceinline__ float sigf(float x) { return 1.f / (1.f + expf(-x)); }

__device__ __forceinline__ void step_init(int tnext, const float* __restrict__ b_a, int i)
{
    // pre-initialize gates / hp for step tnext (split-K GEMMs atomicAdd on top)
    int b = i >> 9, j = i & 511;
    const float* ep = d_embpart + (size_t)tnext * B_ * G4 + b * G4 + j;
    float* g0 = d_g0 + b * G4 + j;
    float* g1 = d_g1 + b * G4 + j;
#pragma unroll
    for (int q = 0; q < 4; q++) {
        g0[q * 512] = ep[q * 512];         // embpart already includes b_ih0+b_hh0
        g1[q * 512] = d_bs1[j + q * 512];
    }
    d_hp[i] = b_a[j];
}

__global__ void initg0_kernel(const float* __restrict__ b_a)
{
    int i = blockIdx.x * blockDim.x + threadIdx.x;
    step_init(0, b_a, i);
}

__global__ void cell0_kernel()
{
    int i = blockIdx.x * blockDim.x + threadIdx.x;   // 0..32767
    int b = i >> 9, j = i & 511;
    const float* g = d_g0 + b * G4;
    float ii = sigf(g[j]);
    float ff = sigf(g[512 + j]);
    float gg = tanhf(g[1024 + j]);
    float oo = sigf(g[1536 + j]);
    float c = ff * d_c0[i] + ii * gg;
    float h = oo * tanhf(c);
    d_c0[i] = c;
    d_x0[b * 1024 + 512 + j] = h;   // h0 for next step's gates0
    d_x1[b * 1024 + j] = h;         // h0n input to gates1
}

__global__ void cell1_kernel(int t, const float* __restrict__ b_a)
{
    int i = blockIdx.x * blockDim.x + threadIdx.x;
    int b = i >> 9, j = i & 511;
    const float* g = d_g1 + b * G4;
    float ii = sigf(g[j]);
    float ff = sigf(g[512 + j]);
    float gg = tanhf(g[1024 + j]);
    float oo = sigf(g[1536 + j]);
    float c = ff * d_c1[i] + ii * gg;
    float h = oo * tanhf(c);
    d_c1[i] = c;
    d_x1[b * 1024 + 512 + j] = h;                      // h1 for next step
    d_hist[((size_t)b * T_ + t) * H_ + j] = h;         // history for logits
    if (t + 1 < T_) step_init(t + 1, b_a, i);
}

// ---------------- one-time prep ------------------------------------------
__global__ void prep_kernel(
    const float* __restrict__ gf,
    const float* __restrict__ W_ih0, const float* __restrict__ W_hh0,
    const float* __restrict__ b_ih0, const float* __restrict__ b_hh0,
    const float* __restrict__ W_ih1, const float* __restrict__ W_hh1,
    const float* __restrict__ b_ih1, const float* __restrict__ b_hh1,
    const int* __restrict__ captions)
{
    int i = blockIdx.x * blockDim.x + threadIdx.x;
    if (i < G4 * 1024) {
        int n = i >> 10, k = i & 1023;
        d_W0[i] = (k < 512) ? W_ih0[n * 1024 + 512 + k] : W_hh0[n * 512 + (k - 512)];
        d_W1[i] = (k < 512) ? W_ih1[n * 512 + k] : W_hh1[n * 512 + (k - 512)];
    }
    if (i < G4) { d_bs0[i] = b_ih0[i] + b_hh0[i]; d_bs1[i] = b_ih1[i] + b_hh1[i]; }
    if (i < T_ * B_) { int t = i / 64, b = i % 64; d_gidx[i] = captions[b * T_ + t]; }
    if (i < B_ * H_) {
        int b = i / H_, j = i % H_;
        float g = gf[i];
        d_x0[b * 1024 + 512 + j] = g;   // h0 init
        d_x1[b * 1024 + 512 + j] = g;   // h1 init
        d_c0[i] = 0.f;
        d_c1[i] = 0.f;
    }
}

// ---------------- launch --------------------------------------------------
extern "C" void kernel_launch(void* const* d_in, const int* in_sizes, int n_in,
                              void* d_out, int out_size)
{
    const float* gf     = (const float*)d_in[0];
    const float* nf     = (const float*)d_in[1];
    const float* emb    = (const float*)d_in[2];
    const float* W_a    = (const float*)d_in[3];
    const float* b_a    = (const float*)d_in[4];
    const float* W_c    = (const float*)d_in[5];
    const float* b_c    = (const float*)d_in[6];
    const float* W_ih0  = (const float*)d_in[7];
    const float* W_hh0  = (const float*)d_in[8];
    const float* b_ih0  = (const float*)d_in[9];
    const float* b_hh0  = (const float*)d_in[10];
    const float* W_ih1  = (const float*)d_in[11];
    const float* W_hh1  = (const float*)d_in[12];
    const float* b_ih1  = (const float*)d_in[13];
    const float* b_hh1  = (const float*)d_in[14];
    const float* W_fc   = (const float*)d_in[15];
    const float* b_fc   = (const float*)d_in[16];
    const int* batch_idx = (const int*)d_in[17];
    const int* captions  = (const int*)d_in[18];
    float* out = (float*)d_out;

    float *node_proj, *embpart, *hist, *x0, *x1, *hp, *g0, *g1, *W0, *W1, *bs0;
    int* gidx;
    cudaGetSymbolAddress((void**)&node_proj, d_node_proj);
    cudaGetSymbolAddress((void**)&embpart,   d_embpart);
    cudaGetSymbolAddress((void**)&hist,      d_hist);
    cudaGetSymbolAddress((void**)&x0,        d_x0);
    cudaGetSymbolAddress((void**)&x1,        d_x1);
    cudaGetSymbolAddress((void**)&hp,        d_hp);
    cudaGetSymbolAddress((void**)&g0,        d_g0);
    cudaGetSymbolAddress((void**)&g1,        d_g1);
    cudaGetSymbolAddress((void**)&W0,        d_W0);
    cudaGetSymbolAddress((void**)&W1,        d_W1);
    cudaGetSymbolAddress((void**)&bs0,       d_bs0);
    cudaGetSymbolAddress((void**)&gidx,      d_gidx);

    // one-time prep: weight concat, bias sums, gather indices, state init
    prep_kernel<<<8192, 256>>>(gf, W_ih0, W_hh0, b_ih0, b_hh0,
                               W_ih1, W_hh1, b_ih1, b_hh1, captions);

    // node_proj = node_features @ W_c^T + b_c         [8192, 512]
    sgemm128<<<dim3(NN_ / 128, H_ / 128), 256>>>(
        nf, H_, W_c, H_, node_proj, H_, b_c, H_, nullptr);

    // embpart = emb[captions] @ W_ih0[:, :512]^T + (b_ih0+b_hh0)   [1280, 2048]
    sgemm128<<<dim3(T_ * B_ / 128, G4 / 128), 256>>>(
        emb, E_, W_ih0, 1024, embpart, G4, bs0, E_, gidx);

    // pre-init gates/hp for step 0
    initg0_kernel<<<64, 512>>>(b_a);

    for (int t = 0; t < T_; t++) {
        // hp = h1 @ W_a^T + b_a        (split-K atomic on pre-inited d_hp)
        sgemm64<<<dim3(1, H_ / 64, 4), 256>>>(
            x1 + 512, 1024, W_a, H_, hp, H_, nullptr, nullptr, H_, nullptr);
        // segment softmax attention -> ctx (into x0[:, :512])
        attn_kernel<<<64, 256>>>(batch_idx);
        // gates0 += [ctx|h0] @ W0cat^T   (pre-inited to embpart[t])
        sgemm64<<<dim3(1, G4 / 64, 4), 256>>>(
            x0, 1024, W0, 1024, g0, G4, nullptr, nullptr, 1024, nullptr);
        cell0_kernel<<<64, 512>>>();
        // gates1 += [h0n|h1] @ W1cat^T   (pre-inited to b_ih1+b_hh1)
        sgemm64<<<dim3(1, G4 / 64, 4), 256>>>(
            x1, 1024, W1, 1024, g1, G4, nullptr, nullptr, 1024, nullptr);
        cell1_kernel<<<64, 512>>>(t, b_a);
    }

    // logits = hist @ W_fc^T + b_fc  -> directly into out[b][t][v]
    sgemm128<<<dim3(B_ * T_ / 128, V_ / 128), 256>>>(
        hist, H_, W_fc, H_, out, V_, b_fc, H_, nullptr);
}

// round 3
// speedup vs baseline: 1.4350x; 1.4350x over previous
#include <cuda_runtime.h>
#include <cuda_bf16.h>
#include <math.h>
#include <stdint.h>

#define B_  64
#define T_  20
#define H_  512
#define E_  512
#define V_  32000
#define NN_ 8192
#define G4  2048   // 4*H

// ---------------- static scratch (no allocations allowed) ----------------
__device__ float d_node_proj[NN_ * H_];
__device__ float d_embpart[T_ * B_ * G4];
__device__ float d_hist[B_ * T_ * H_];
__device__ float d_x0[B_ * 1024];
__device__ float d_x1[B_ * 1024];
__device__ float d_c0[B_ * H_];
__device__ float d_c1[B_ * H_];
__device__ float d_hp[B_ * H_];
__device__ float d_g0[B_ * G4];
__device__ float d_g1[B_ * G4];
__device__ float d_W0[G4 * 1024];
__device__ float d_W1[G4 * 1024];
__device__ float d_bs0[G4];
__device__ float d_bs1[G4];
__device__ int   d_gidx[T_ * B_];

// ===================== mma.sync helpers (sm_80 baseline) =================
__device__ __forceinline__ uint32_t smem_u32(const void* p) {
    uint32_t a;
    asm("{ .reg .u64 t; cvta.to.shared.u64 t, %1; cvt.u32.u64 %0, t; }"
        : "=r"(a) : "l"(p));
    return a;
}
__device__ __forceinline__ void ldsm4(uint32_t* r, uint32_t addr) {
    asm volatile("ldmatrix.sync.aligned.m8n8.x4.shared.b16 {%0,%1,%2,%3}, [%4];"
                 : "=r"(r[0]), "=r"(r[1]), "=r"(r[2]), "=r"(r[3]) : "r"(addr));
}
__device__ __forceinline__ void ldsm2(uint32_t* r, uint32_t addr) {
    asm volatile("ldmatrix.sync.aligned.m8n8.x2.shared.b16 {%0,%1}, [%2];"
                 : "=r"(r[0]), "=r"(r[1]) : "r"(addr));
}
__device__ __forceinline__ void mma_bf16(float* d, const uint32_t* a, const uint32_t* b) {
    asm volatile(
        "mma.sync.aligned.m16n8k16.row.col.f32.bf16.bf16.f32 "
        "{%0,%1,%2,%3}, {%4,%5,%6,%7}, {%8,%9}, {%0,%1,%2,%3};"
        : "+f"(d[0]), "+f"(d[1]), "+f"(d[2]), "+f"(d[3])
        : "r"(a[0]), "r"(a[1]), "r"(a[2]), "r"(a[3]), "r"(b[0]), "r"(b[1]));
}
__device__ __forceinline__ void split4(float4 a, uint2& hi, uint2& lo) {
    __nv_bfloat16 h0 = __float2bfloat16(a.x), h1 = __float2bfloat16(a.y);
    __nv_bfloat16 h2 = __float2bfloat16(a.z), h3 = __float2bfloat16(a.w);
    __nv_bfloat16 l0 = __float2bfloat16(a.x - __bfloat162float(h0));
    __nv_bfloat16 l1 = __float2bfloat16(a.y - __bfloat162float(h1));
    __nv_bfloat16 l2 = __float2bfloat16(a.z - __bfloat162float(h2));
    __nv_bfloat16 l3 = __float2bfloat16(a.w - __bfloat162float(h3));
    __nv_bfloat162 ph = __nv_bfloat162(h0, h1), qh = __nv_bfloat162(h2, h3);
    __nv_bfloat162 pl = __nv_bfloat162(l0, l1), ql = __nv_bfloat162(l2, l3);
    hi = make_uint2(*(uint32_t*)&ph, *(uint32_t*)&qh);
    lo = make_uint2(*(uint32_t*)&pl, *(uint32_t*)&ql);
}

// ========== split-bf16 tensor-core GEMM: C = A @ B^T (+bias) =============
// A [M,K] fp32 (optional row gather via gidx), B [N,K] fp32, C [M,N] fp32.
// Tile 128x128, BK=32, padded bf16 smem (stride 40 = 80B, 16B aligned,
// conflict-free ldmatrix), double buffered, fp32 register accumulators.
// Smem stage layout: Ah(10240) Al(10240) Bh(10240) Bl(10240) = 40960 B.
#define TG_STAGE 40960
#define TG_SMEM  (2 * TG_STAGE)

__global__ void __launch_bounds__(256, 1) tgemm(
    const float* __restrict__ A, int lda,
    const float* __restrict__ Bw, int ldb,
    float* __restrict__ C, int ldc,
    const float* __restrict__ bias,
    int K, const int* __restrict__ gidx)
{
    extern __shared__ char sm[];
    const uint32_t sbase = smem_u32(sm);
    const int tid = threadIdx.x;
    const int lane = tid & 31, wid = tid >> 5;
    const int wm = wid & 1, wn = wid >> 1;     // warp grid 2 (M) x 4 (N)
    const int m0 = blockIdx.x * 128, n0 = blockIdx.y * 128;

    // gmem load coords: 4 float4 per thread per matrix per chunk
    const int lrow = tid >> 3;                 // 0..31, +32 per v
    const int c4 = (tid & 7) << 2;             // k offset within chunk

    // ldmatrix per-lane byte offsets within a tile
    const uint32_t aLane = (((uint32_t)(lane & 15) * 40u) + ((lane >> 4) * 8u)) * 2u;
    const uint32_t bLane = (((uint32_t)(lane & 7) * 40u) + (((lane >> 3) & 1) * 8u)) * 2u;

    float acc[4][4][4];
#pragma unroll
    for (int i = 0; i < 4; i++)
#pragma unroll
        for (int j = 0; j < 4; j++)
#pragma unroll
            for (int q = 0; q < 4; q++) acc[i][j][q] = 0.f;

    const int nch = K >> 5;
    float4 ga[4], gb[4];

    // ---- load chunk 0 ----
#pragma unroll
    for (int v = 0; v < 4; v++) {
        int row = lrow + v * 32;
        int gr = gidx ? gidx[m0 + row] : (m0 + row);
        ga[v] = *(const float4*)(A + (size_t)gr * lda + c4);
        gb[v] = *(const float4*)(Bw + (size_t)(n0 + row) * ldb + c4);
    }
#pragma unroll
    for (int v = 0; v < 4; v++) {
        int row = lrow + v * 32;
        uint32_t off = ((uint32_t)row * 40u + (uint32_t)c4) * 2u;
        uint2 hi, lo;
        split4(ga[v], hi, lo);
        *(uint2*)(sm + off) = hi;
        *(uint2*)(sm + 10240 + off) = lo;
        split4(gb[v], hi, lo);
        *(uint2*)(sm + 20480 + off) = hi;
        *(uint2*)(sm + 30720 + off) = lo;
    }
    __syncthreads();

    for (int ich = 0; ich < nch; ich++) {
        const bool pf = (ich + 1 < nch);
        if (pf) {
            const int kb = (ich + 1) << 5;
#pragma unroll
            for (int v = 0; v < 4; v++) {
                int row = lrow + v * 32;
                int gr = gidx ? gidx[m0 + row] : (m0 + row);
                ga[v] = *(const float4*)(A + (size_t)gr * lda + kb + c4);
                gb[v] = *(const float4*)(Bw + (size_t)(n0 + row) * ldb + kb + c4);
            }
        }

        // ---- compute on stage ich&1 ----
        const uint32_t st = sbase + (uint32_t)(ich & 1) * TG_STAGE;
#pragma unroll
        for (int kk = 0; kk < 2; kk++) {
            uint32_t Ah[4][4], Al[4][4], Bh[4][2], Bl[4][2];
#pragma unroll
            for (int ma = 0; ma < 4; ma++) {
                uint32_t ad = st + (uint32_t)(wm * 64 + ma * 16) * 80u + aLane + kk * 32u;
                ldsm4(Ah[ma], ad);
                ldsm4(Al[ma], ad + 10240u);
            }
#pragma unroll
            for (int na = 0; na < 4; na++) {
                uint32_t bd = st + 20480u + (uint32_t)(wn * 32 + na * 8) * 80u + bLane + kk * 32u;
                ldsm2(Bh[na], bd);
                ldsm2(Bl[na], bd + 10240u);
            }
#pragma unroll
            for (int ma = 0; ma < 4; ma++)
#pragma unroll
                for (int na = 0; na < 4; na++) {
                    mma_bf16(acc[ma][na], Ah[ma], Bh[na]);
                    mma_bf16(acc[ma][na], Al[ma], Bh[na]);
                    mma_bf16(acc[ma][na], Ah[ma], Bl[na]);
                }
        }

        if (pf) {
            char* dstS = sm + ((ich + 1) & 1) * TG_STAGE;
#pragma unroll
            for (int v = 0; v < 4; v++) {
                int row = lrow + v * 32;
                uint32_t off = ((uint32_t)row * 40u + (uint32_t)c4) * 2u;
                uint2 hi, lo;
                split4(ga[v], hi, lo);
                *(uint2*)(dstS + off) = hi;
                *(uint2*)(dstS + 10240 + off) = lo;
                split4(gb[v], hi, lo);
                *(uint2*)(dstS + 20480 + off) = hi;
                *(uint2*)(dstS + 30720 + off) = lo;
            }
        }
        __syncthreads();
    }

    // ---- epilogue ----
    const int g = lane >> 2, t = lane & 3;
#pragma unroll
    for (int ma = 0; ma < 4; ma++) {
        int r = m0 + wm * 64 + ma * 16 + g;
#pragma unroll
        for (int na = 0; na < 4; na++) {
            int c = n0 + wn * 32 + na * 8 + 2 * t;
            float2 bb = make_float2(0.f, 0.f);
            if (bias) bb = *(const float2*)(bias + c);
            *(float2*)(C + (size_t)r * ldc + c) =
                make_float2(acc[ma][na][0] + bb.x, acc[ma][na][1] + bb.y);
            *(float2*)(C + (size_t)(r + 8) * ldc + c) =
                make_float2(acc[ma][na][2] + bb.x, acc[ma][na][3] + bb.y);
        }
    }
}

// ---------------- generic 64x64 SGEMM, split-K via gridDim.z -------------
__global__ __launch_bounds__(256) void sgemm64(
    const float* __restrict__ A, int lda,
    const float* __restrict__ Bw, int ldb,
    float* __restrict__ C, int ldc,
    int K)
{
    __shared__ float As[16][68];
    __shared__ float Bs[16][68];
    const int tid = threadIdx.x;
    const int m0 = blockIdx.x * 64;
    const int n0 = blockIdx.y * 64;
    const int Kc = K / gridDim.z;
    const int kbeg = blockIdx.z * Kc;
    const int kend = kbeg + Kc;

    const int ar = tid >> 2;
    const int ak = (tid & 3) << 2;
    const float* Ap = A + (size_t)(m0 + ar) * lda + ak;
    const float* Bp = Bw + (size_t)(n0 + ar) * ldb + ak;
    const int tx = tid & 15, ty = tid >> 4;

    float acc[4][4];
#pragma unroll
    for (int i = 0; i < 4; i++)
#pragma unroll
        for (int j = 0; j < 4; j++) acc[i][j] = 0.f;

    for (int k0 = kbeg; k0 < kend; k0 += 16) {
        float4 av = *(const float4*)(Ap + k0);
        float4 bv = *(const float4*)(Bp + k0);
        As[ak + 0][ar] = av.x; As[ak + 1][ar] = av.y;
        As[ak + 2][ar] = av.z; As[ak + 3][ar] = av.w;
        Bs[ak + 0][ar] = bv.x; Bs[ak + 1][ar] = bv.y;
        Bs[ak + 2][ar] = bv.z; Bs[ak + 3][ar] = bv.w;
        __syncthreads();
#pragma unroll
        for (int kk = 0; kk < 16; kk++) {
            float a_[4], b_[4];
            *(float4*)a_ = *(const float4*)&As[kk][ty << 2];
            *(float4*)b_ = *(const float4*)&Bs[kk][tx << 2];
#pragma unroll
            for (int i = 0; i < 4; i++)
#pragma unroll
                for (int j = 0; j < 4; j++)
                    acc[i][j] = fmaf(a_[i], b_[j], acc[i][j]);
        }
        __syncthreads();
    }

#pragma unroll
    for (int i = 0; i < 4; i++) {
        int r = m0 + (ty << 2) + i;
        float* cp = C + (size_t)r * ldc + n0 + (tx << 2);
        atomicAdd(cp + 0, acc[i][0]); atomicAdd(cp + 1, acc[i][1]);
        atomicAdd(cp + 2, acc[i][2]); atomicAdd(cp + 3, acc[i][3]);
    }
}

// ---------------- attention: segment online-softmax, ctx in registers ----
__device__ __forceinline__ int lowbound(const int* __restrict__ a, int n, int v)
{
    int lo = 0, hi = n;
    while (lo < hi) { int mid = (lo + hi) >> 1; if (a[mid] < v) lo = mid + 1; else hi = mid; }
    return lo;
}

__global__ __launch_bounds__(256) void attn_kernel(const int* __restrict__ batch_idx)
{
    const int b = blockIdx.x;
    __shared__ float sh_hp[512];
    __shared__ float sh_ctx[8][512];
    __shared__ float sh_m[8], sh_s[8];
    const int tid = threadIdx.x, lane = tid & 31, w = tid >> 5;

    for (int i = tid; i < 512; i += 256) sh_hp[i] = d_hp[b * 512 + i];
    __syncthreads();

    const int s0 = lowbound(batch_idx, NN_, b);
    const int s1 = lowbound(batch_idx, NN_, b + 1);

    float m = -INFINITY, ssum = 0.f;
    float ctx[16];
#pragma unroll
    for (int i = 0; i < 16; i++) ctx[i] = 0.f;

    for (int n = s0 + w; n < s1; n += 8) {
        const float* np = d_node_proj + (size_t)n * 512;
        float v[16]; float p = 0.f;
#pragma unroll
        for (int i = 0; i < 16; i++) {
            v[i] = np[lane + 32 * i];
            p = fmaf(v[i], sh_hp[lane + 32 * i], p);
        }
#pragma unroll
        for (int o = 16; o > 0; o >>= 1) p += __shfl_xor_sync(0xffffffffu, p, o);
        float mn = fmaxf(m, p);
        float scale = expf(m - mn);
        float e = expf(p - mn);
        ssum = ssum * scale + e;
#pragma unroll
        for (int i = 0; i < 16; i++) ctx[i] = ctx[i] * scale + e * v[i];
        m = mn;
    }

#pragma unroll
    for (int i = 0; i < 16; i++) sh_ctx[w][lane + 32 * i] = ctx[i];
    if (lane == 0) { sh_m[w] = m; sh_s[w] = ssum; }
    __syncthreads();

    float M = -INFINITY;
#pragma unroll
    for (int ww = 0; ww < 8; ww++) M = fmaxf(M, sh_m[ww]);
    if (M == -INFINITY) {
        for (int j = tid; j < 512; j += 256) d_x0[b * 1024 + j] = 0.f;
        return;
    }
    float stot = 0.f;
    float ew[8];
#pragma unroll
    for (int ww = 0; ww < 8; ww++) { ew[ww] = expf(sh_m[ww] - M); stot += sh_s[ww] * ew[ww]; }
    float inv = 1.f / stot;
    for (int j = tid; j < 512; j += 256) {
        float num = 0.f;
#pragma unroll
        for (int ww = 0; ww < 8; ww++) num = fmaf(sh_ctx[ww][j], ew[ww], num);
        d_x0[b * 1024 + j] = num * inv;
    }
}

// ---------------- LSTM cells + next-step gate init -----------------------
__device__ __forceinline__ float sigf(float x) { return 1.f / (1.f + expf(-x)); }

__device__ __forceinline__ void step_init(int tnext, const float* __restrict__ b_a, int i)
{
    int b = i >> 9, j = i & 511;
    const float* ep = d_embpart + (size_t)tnext * B_ * G4 + b * G4 + j;
    float* g0 = d_g0 + b * G4 + j;
    float* g1 = d_g1 + b * G4 + j;
#pragma unroll
    for (int q = 0; q < 4; q++) {
        g0[q * 512] = ep[q * 512];
        g1[q * 512] = d_bs1[j + q * 512];
    }
    d_hp[i] = b_a[j];
}

__global__ void initg0_kernel(const float* __restrict__ b_a)
{
    int i = blockIdx.x * blockDim.x + threadIdx.x;
    step_init(0, b_a, i);
}

__global__ void cell0_kernel()
{
    int i = blockIdx.x * blockDim.x + threadIdx.x;
    int b = i >> 9, j = i & 511;
    const float* g = d_g0 + b * G4;
    float ii = sigf(g[j]);
    float ff = sigf(g[512 + j]);
    float gg = tanhf(g[1024 + j]);
    float oo = sigf(g[1536 + j]);
    float c = ff * d_c0[i] + ii * gg;
    float h = oo * tanhf(c);
    d_c0[i] = c;
    d_x0[b * 1024 + 512 + j] = h;
    d_x1[b * 1024 + j] = h;
}

__global__ void cell1_kernel(int t, const float* __restrict__ b_a)
{
    int i = blockIdx.x * blockDim.x + threadIdx.x;
    int b = i >> 9, j = i & 511;
    const float* g = d_g1 + b * G4;
    float ii = sigf(g[j]);
    float ff = sigf(g[512 + j]);
    float gg = tanhf(g[1024 + j]);
    float oo = sigf(g[1536 + j]);
    float c = ff * d_c1[i] + ii * gg;
    float h = oo * tanhf(c);
    d_c1[i] = c;
    d_x1[b * 1024 + 512 + j] = h;
    d_hist[((size_t)b * T_ + t) * H_ + j] = h;
    if (t + 1 < T_) step_init(t + 1, b_a, i);
}

// ---------------- one-time prep ------------------------------------------
__global__ void prep_kernel(
    const float* __restrict__ gf,
    const float* __restrict__ W_ih0, const float* __restrict__ W_hh0,
    const float* __restrict__ b_ih0, const float* __restrict__ b_hh0,
    const float* __restrict__ W_ih1, const float* __restrict__ W_hh1,
    const float* __restrict__ b_ih1, const float* __restrict__ b_hh1,
    const int* __restrict__ captions)
{
    int i = blockIdx.x * blockDim.x + threadIdx.x;
    if (i < G4 * 1024) {
        int n = i >> 10, k = i & 1023;
        d_W0[i] = (k < 512) ? W_ih0[n * 1024 + 512 + k] : W_hh0[n * 512 + (k - 512)];
        d_W1[i] = (k < 512) ? W_ih1[n * 512 + k] : W_hh1[n * 512 + (k - 512)];
    }
    if (i < G4) { d_bs0[i] = b_ih0[i] + b_hh0[i]; d_bs1[i] = b_ih1[i] + b_hh1[i]; }
    if (i < T_ * B_) { int t = i / 64, b = i % 64; d_gidx[i] = captions[b * T_ + t]; }
    if (i < B_ * H_) {
        int b = i / H_, j = i % H_;
        float g = gf[i];
        d_x0[b * 1024 + 512 + j] = g;
        d_x1[b * 1024 + 512 + j] = g;
        d_c0[i] = 0.f;
        d_c1[i] = 0.f;
    }
}

// ---------------- launch --------------------------------------------------
extern "C" void kernel_launch(void* const* d_in, const int* in_sizes, int n_in,
                              void* d_out, int out_size)
{
    const float* gf     = (const float*)d_in[0];
    const float* nf     = (const float*)d_in[1];
    const float* emb    = (const float*)d_in[2];
    const float* W_a    = (const float*)d_in[3];
    const float* b_a    = (const float*)d_in[4];
    const float* W_c    = (const float*)d_in[5];
    const float* b_c    = (const float*)d_in[6];
    const float* W_ih0  = (const float*)d_in[7];
    const float* W_hh0  = (const float*)d_in[8];
    const float* b_ih0  = (const float*)d_in[9];
    const float* b_hh0  = (const float*)d_in[10];
    const float* W_ih1  = (const float*)d_in[11];
    const float* W_hh1  = (const float*)d_in[12];
    const float* b_ih1  = (const float*)d_in[13];
    const float* b_hh1  = (const float*)d_in[14];
    const float* W_fc   = (const float*)d_in[15];
    const float* b_fc   = (const float*)d_in[16];
    const int* batch_idx = (const int*)d_in[17];
    const int* captions  = (const int*)d_in[18];
    float* out = (float*)d_out;

    float *node_proj, *embpart, *hist, *x0, *x1, *hp, *g0, *g1, *W0, *W1, *bs0;
    int* gidx;
    cudaGetSymbolAddress((void**)&node_proj, d_node_proj);
    cudaGetSymbolAddress((void**)&embpart,   d_embpart);
    cudaGetSymbolAddress((void**)&hist,      d_hist);
    cudaGetSymbolAddress((void**)&x0,        d_x0);
    cudaGetSymbolAddress((void**)&x1,        d_x1);
    cudaGetSymbolAddress((void**)&hp,        d_hp);
    cudaGetSymbolAddress((void**)&g0,        d_g0);
    cudaGetSymbolAddress((void**)&g1,        d_g1);
    cudaGetSymbolAddress((void**)&W0,        d_W0);
    cudaGetSymbolAddress((void**)&W1,        d_W1);
    cudaGetSymbolAddress((void**)&bs0,       d_bs0);
    cudaGetSymbolAddress((void**)&gidx,      d_gidx);

    cudaFuncSetAttribute(tgemm, cudaFuncAttributeMaxDynamicSharedMemorySize, TG_SMEM);

    // one-time prep: weight concat, bias sums, gather indices, state init
    prep_kernel<<<8192, 256>>>(gf, W_ih0, W_hh0, b_ih0, b_hh0,
                               W_ih1, W_hh1, b_ih1, b_hh1, captions);

    // node_proj = node_features @ W_c^T + b_c         [8192, 512]
    tgemm<<<dim3(NN_ / 128, H_ / 128), 256, TG_SMEM>>>(
        nf, H_, W_c, H_, node_proj, H_, b_c, H_, nullptr);

    // embpart = emb[captions] @ W_ih0[:, :512]^T + (b_ih0+b_hh0)   [1280, 2048]
    tgemm<<<dim3(T_ * B_ / 128, G4 / 128), 256, TG_SMEM>>>(
        emb, E_, W_ih0, 1024, embpart, G4, bs0, E_, gidx);

    // pre-init gates/hp for step 0
    initg0_kernel<<<64, 512>>>(b_a);

    for (int t = 0; t < T_; t++) {
        sgemm64<<<dim3(1, H_ / 64, 4), 256>>>(
            x1 + 512, 1024, W_a, H_, hp, H_, H_);
        attn_kernel<<<64, 256>>>(batch_idx);
        sgemm64<<<dim3(1, G4 / 64, 4), 256>>>(
            x0, 1024, W0, 1024, g0, G4, 1024);
        cell0_kernel<<<64, 512>>>();
        sgemm64<<<dim3(1, G4 / 64, 4), 256>>>(
            x1, 1024, W1, 1024, g1, G4, 1024);
        cell1_kernel<<<64, 512>>>(t, b_a);
    }

    // logits = hist @ W_fc^T + b_fc  -> directly into out[b][t][v]
    tgemm<<<dim3(B_ * T_ / 128, V_ / 128), 256, TG_SMEM>>>(
        hist, H_, W_fc, H_, out, V_, b_fc, H_, nullptr);
}

// round 4
// speedup vs baseline: 2.0211x; 1.4084x over previous
#include <cuda_runtime.h>
#include <cuda_bf16.h>
#include <math.h>
#include <stdint.h>

#define B_  64
#define T_  20
#define H_  512
#define E_  512
#define V_  32000
#define NN_ 8192
#define G4  2048   // 4*H
#define NB  148    // persistent grid (<= SM count, 1 wave resident)

// ---------------- static scratch (no allocations allowed) ----------------
__device__ float d_node_proj[NN_ * H_];
__device__ float d_embpart[T_ * B_ * G4];     // emb@Wih0_E^T + b_ih0+b_hh0
__device__ float d_hist[B_ * T_ * H_];
__device__ float d_c0[B_ * H_];
__device__ float d_c1[B_ * H_];
__device__ float d_bs0[G4];
__device__ float d_bs1[G4];
__device__ int   d_gidx[T_ * B_];

// bf16 hi/lo split weights (one-time) and activations (per-step)
__device__ __nv_bfloat16 d_Wah[H_ * H_], d_Wal[H_ * H_];
__device__ __nv_bfloat16 d_W0h[G4 * 1024], d_W0l[G4 * 1024];
__device__ __nv_bfloat16 d_W1h[G4 * 1024], d_W1l[G4 * 1024];
__device__ __nv_bfloat16 d_xah[B_ * 1024], d_xal[B_ * 1024];  // [ctx | h0]
__device__ __nv_bfloat16 d_xbh[B_ * 1024], d_xbl[B_ * 1024];  // [h0n | h1]

// split-K partial buffers (deterministic, no atomics)
__device__ float d_hppart[8 * B_ * H_];
__device__ float d_gpart0[4 * B_ * G4];
__device__ float d_gpart1[4 * B_ * G4];
__device__ unsigned g_cnt;   // global barrier counter (reset in prep)

// ===================== helpers =====================
__device__ __forceinline__ uint32_t smem_u32(const void* p) {
    uint32_t a;
    asm("{ .reg .u64 t; cvta.to.shared.u64 t, %1; cvt.u32.u64 %0, t; }"
        : "=r"(a) : "l"(p));
    return a;
}
__device__ __forceinline__ void ldsm4(uint32_t* r, uint32_t addr) {
    asm volatile("ldmatrix.sync.aligned.m8n8.x4.shared.b16 {%0,%1,%2,%3}, [%4];"
                 : "=r"(r[0]), "=r"(r[1]), "=r"(r[2]), "=r"(r[3]) : "r"(addr));
}
__device__ __forceinline__ void ldsm2(uint32_t* r, uint32_t addr) {
    asm volatile("ldmatrix.sync.aligned.m8n8.x2.shared.b16 {%0,%1}, [%2];"
                 : "=r"(r[0]), "=r"(r[1]) : "r"(addr));
}
__device__ __forceinline__ void mma_bf16(float* d, const uint32_t* a, const uint32_t* b) {
    asm volatile(
        "mma.sync.aligned.m16n8k16.row.col.f32.bf16.bf16.f32 "
        "{%0,%1,%2,%3}, {%4,%5,%6,%7}, {%8,%9}, {%0,%1,%2,%3};"
        : "+f"(d[0]), "+f"(d[1]), "+f"(d[2]), "+f"(d[3])
        : "r"(a[0]), "r"(a[1]), "r"(a[2]), "r"(a[3]), "r"(b[0]), "r"(b[1]));
}
__device__ __forceinline__ void split1(float v, __nv_bfloat16& h, __nv_bfloat16& l) {
    h = __float2bfloat16(v);
    l = __float2bfloat16(v - __bfloat162float(h));
}
__device__ __forceinline__ void split4(float4 a, uint2& hi, uint2& lo) {
    __nv_bfloat16 h0, h1, h2, h3, l0, l1, l2, l3;
    split1(a.x, h0, l0); split1(a.y, h1, l1);
    split1(a.z, h2, l2); split1(a.w, h3, l3);
    __nv_bfloat162 ph = __nv_bfloat162(h0, h1), qh = __nv_bfloat162(h2, h3);
    __nv_bfloat162 pl = __nv_bfloat162(l0, l1), ql = __nv_bfloat162(l2, l3);
    hi = make_uint2(*(uint32_t*)&ph, *(uint32_t*)&qh);
    lo = make_uint2(*(uint32_t*)&pl, *(uint32_t*)&ql);
}
__device__ __forceinline__ float sigf(float x) { return 1.f / (1.f + expf(-x)); }

// ========== big split-bf16 HMMA GEMM (unchanged from R3) =================
#define TG_STAGE 40960
#define TG_SMEM  (2 * TG_STAGE)

__global__ void __launch_bounds__(256, 1) tgemm(
    const float* __restrict__ A, int lda,
    const float* __restrict__ Bw, int ldb,
    float* __restrict__ C, int ldc,
    const float* __restrict__ bias,
    int K, const int* __restrict__ gidx)
{
    extern __shared__ char sm[];
    const uint32_t sbase = smem_u32(sm);
    const int tid = threadIdx.x;
    const int lane = tid & 31, wid = tid >> 5;
    const int wm = wid & 1, wn = wid >> 1;
    const int m0 = blockIdx.x * 128, n0 = blockIdx.y * 128;
    const int lrow = tid >> 3;
    const int c4 = (tid & 7) << 2;
    const uint32_t aLane = (((uint32_t)(lane & 15) * 40u) + ((lane >> 4) * 8u)) * 2u;
    const uint32_t bLane = (((uint32_t)(lane & 7) * 40u) + (((lane >> 3) & 1) * 8u)) * 2u;

    float acc[4][4][4];
#pragma unroll
    for (int i = 0; i < 4; i++)
#pragma unroll
        for (int j = 0; j < 4; j++)
#pragma unroll
            for (int q = 0; q < 4; q++) acc[i][j][q] = 0.f;

    const int nch = K >> 5;
    float4 ga[4], gb[4];
#pragma unroll
    for (int v = 0; v < 4; v++) {
        int row = lrow + v * 32;
        int gr = gidx ? gidx[m0 + row] : (m0 + row);
        ga[v] = *(const float4*)(A + (size_t)gr * lda + c4);
        gb[v] = *(const float4*)(Bw + (size_t)(n0 + row) * ldb + c4);
    }
#pragma unroll
    for (int v = 0; v < 4; v++) {
        int row = lrow + v * 32;
        uint32_t off = ((uint32_t)row * 40u + (uint32_t)c4) * 2u;
        uint2 hi, lo;
        split4(ga[v], hi, lo);
        *(uint2*)(sm + off) = hi;
        *(uint2*)(sm + 10240 + off) = lo;
        split4(gb[v], hi, lo);
        *(uint2*)(sm + 20480 + off) = hi;
        *(uint2*)(sm + 30720 + off) = lo;
    }
    __syncthreads();

    for (int ich = 0; ich < nch; ich++) {
        const bool pf = (ich + 1 < nch);
        if (pf) {
            const int kb = (ich + 1) << 5;
#pragma unroll
            for (int v = 0; v < 4; v++) {
                int row = lrow + v * 32;
                int gr = gidx ? gidx[m0 + row] : (m0 + row);
                ga[v] = *(const float4*)(A + (size_t)gr * lda + kb + c4);
                gb[v] = *(const float4*)(Bw + (size_t)(n0 + row) * ldb + kb + c4);
            }
        }
        const uint32_t st = sbase + (uint32_t)(ich & 1) * TG_STAGE;
#pragma unroll
        for (int kk = 0; kk < 2; kk++) {
            uint32_t Ah[4][4], Al[4][4], Bh[4][2], Bl[4][2];
#pragma unroll
            for (int ma = 0; ma < 4; ma++) {
                uint32_t ad = st + (uint32_t)(wm * 64 + ma * 16) * 80u + aLane + kk * 32u;
                ldsm4(Ah[ma], ad);
                ldsm4(Al[ma], ad + 10240u);
            }
#pragma unroll
            for (int na = 0; na < 4; na++) {
                uint32_t bd = st + 20480u + (uint32_t)(wn * 32 + na * 8) * 80u + bLane + kk * 32u;
                ldsm2(Bh[na], bd);
                ldsm2(Bl[na], bd + 10240u);
            }
#pragma unroll
            for (int ma = 0; ma < 4; ma++)
#pragma unroll
                for (int na = 0; na < 4; na++) {
                    mma_bf16(acc[ma][na], Ah[ma], Bh[na]);
                    mma_bf16(acc[ma][na], Al[ma], Bh[na]);
                    mma_bf16(acc[ma][na], Ah[ma], Bl[na]);
                }
        }
        if (pf) {
            char* dstS = sm + ((ich + 1) & 1) * TG_STAGE;
#pragma unroll
            for (int v = 0; v < 4; v++) {
                int row = lrow + v * 32;
                uint32_t off = ((uint32_t)row * 40u + (uint32_t)c4) * 2u;
                uint2 hi, lo;
                split4(ga[v], hi, lo);
                *(uint2*)(dstS + off) = hi;
                *(uint2*)(dstS + 10240 + off) = lo;
                split4(gb[v], hi, lo);
                *(uint2*)(dstS + 20480 + off) = hi;
                *(uint2*)(dstS + 30720 + off) = lo;
            }
        }
        __syncthreads();
    }

    const int g = lane >> 2, t = lane & 3;
#pragma unroll
    for (int ma = 0; ma < 4; ma++) {
        int r = m0 + wm * 64 + ma * 16 + g;
#pragma unroll
        for (int na = 0; na < 4; na++) {
            int c = n0 + wn * 32 + na * 8 + 2 * t;
            float2 bb = make_float2(0.f, 0.f);
            if (bias) bb = *(const float2*)(bias + c);
            *(float2*)(C + (size_t)r * ldc + c) =
                make_float2(acc[ma][na][0] + bb.x, acc[ma][na][1] + bb.y);
            *(float2*)(C + (size_t)(r + 8) * ldc + c) =
                make_float2(acc[ma][na][2] + bb.x, acc[ma][na][3] + bb.y);
        }
    }
}

// ==================== persistent recurrence kernel =======================
struct AttnSh {
    float hp[512];
    float ctx[8][512];
    float m[8], s[8];
};
union RecSh {
    __nv_bfloat16 g[4 * 64 * 40];   // Ah | Al | Bh | Bl tiles
    AttnSh a;
};

__device__ __forceinline__ void gbar(unsigned& bar)
{
    bar += NB;
    __threadfence();
    __syncthreads();
    if (threadIdx.x == 0) {
        atomicAdd(&g_cnt, 1u);
        volatile unsigned* pc = &g_cnt;
        while (*pc < bar) { __nanosleep(64); }
    }
    __syncthreads();
}

// 64xN HMMA task: C_partial[64, 64 cols at n0] += Ahl[64, kbeg:kbeg+klen] @ Bhl^T
__device__ __forceinline__ void gemm64_hmma(
    const __nv_bfloat16* __restrict__ Agh, const __nv_bfloat16* __restrict__ Agl, int lda,
    int kbeg, int klen,
    const __nv_bfloat16* __restrict__ Bgh, const __nv_bfloat16* __restrict__ Bgl,
    int ldb, int n0,
    float* __restrict__ Cp, int ldc, __nv_bfloat16* sms)
{
    __nv_bfloat16* sAh = sms;
    __nv_bfloat16* sAl = sms + 64 * 40;
    __nv_bfloat16* sBh = sms + 2 * 64 * 40;
    __nv_bfloat16* sBl = sms + 3 * 64 * 40;
    const uint32_t uAh = smem_u32(sAh), uAl = smem_u32(sAl);
    const uint32_t uBh = smem_u32(sBh), uBl = smem_u32(sBl);

    const int tid = threadIdx.x, lane = tid & 31, wid = tid >> 5;
    const int wm = wid & 1, wn = wid >> 1;
    const int grow = tid >> 2, gcol = (tid & 3) << 3;
    const uint32_t aLane = (uint32_t)(((lane & 15) * 40 + (lane >> 4) * 8) * 2);
    const uint32_t bLane = (uint32_t)(((lane & 7) * 40 + ((lane >> 3) & 1) * 8) * 2);

    float acc[2][2][4];
#pragma unroll
    for (int i = 0; i < 2; i++)
#pragma unroll
        for (int j = 0; j < 2; j++)
#pragma unroll
            for (int q = 0; q < 4; q++) acc[i][j][q] = 0.f;

    for (int kb = kbeg; kb < kbeg + klen; kb += 32) {
        uint4 ah = __ldcg((const uint4*)(Agh + (size_t)grow * lda + kb + gcol));
        uint4 al = __ldcg((const uint4*)(Agl + (size_t)grow * lda + kb + gcol));
        uint4 bh = *(const uint4*)(Bgh + (size_t)(n0 + grow) * ldb + kb + gcol);
        uint4 bl = *(const uint4*)(Bgl + (size_t)(n0 + grow) * ldb + kb + gcol);
        __syncthreads();
        uint32_t so = (uint32_t)(grow * 40 + gcol) * 2;
        *(uint4*)((char*)sAh + so) = ah;
        *(uint4*)((char*)sAl + so) = al;
        *(uint4*)((char*)sBh + so) = bh;
        *(uint4*)((char*)sBl + so) = bl;
        __syncthreads();
#pragma unroll
        for (int kk = 0; kk < 2; kk++) {
            uint32_t Ahf[2][4], Alf[2][4], Bhf[2][2], Blf[2][2];
#pragma unroll
            for (int ma = 0; ma < 2; ma++) {
                uint32_t ro = (uint32_t)(wm * 32 + ma * 16) * 80u + aLane + kk * 32u;
                ldsm4(Ahf[ma], uAh + ro);
                ldsm4(Alf[ma], uAl + ro);
            }
#pragma unroll
            for (int na = 0; na < 2; na++) {
                uint32_t co = (uint32_t)(wn * 16 + na * 8) * 80u + bLane + kk * 32u;
                ldsm2(Bhf[na], uBh + co);
                ldsm2(Blf[na], uBl + co);
            }
#pragma unroll
            for (int ma = 0; ma < 2; ma++)
#pragma unroll
                for (int na = 0; na < 2; na++) {
                    mma_bf16(acc[ma][na], Ahf[ma], Bhf[na]);
                    mma_bf16(acc[ma][na], Alf[ma], Bhf[na]);
                    mma_bf16(acc[ma][na], Ahf[ma], Blf[na]);
                }
        }
    }
    const int gq = lane >> 2, qt = lane & 3;
#pragma unroll
    for (int ma = 0; ma < 2; ma++) {
        int r = wm * 32 + ma * 16 + gq;
#pragma unroll
        for (int na = 0; na < 2; na++) {
            int c = n0 + wn * 16 + na * 8 + qt * 2;
            *(float2*)(Cp + (size_t)r * ldc + c) =
                make_float2(acc[ma][na][0], acc[ma][na][1]);
            *(float2*)(Cp + (size_t)(r + 8) * ldc + c) =
                make_float2(acc[ma][na][2], acc[ma][na][3]);
        }
    }
}

__device__ __forceinline__ int lowbound(const int* __restrict__ a, int n, int v)
{
    int lo = 0, hi = n;
    while (lo < hi) { int mid = (lo + hi) >> 1; if (a[mid] < v) lo = mid + 1; else hi = mid; }
    return lo;
}

__device__ __forceinline__ void attn_phase(int b, const int* __restrict__ batch_idx,
                                           const float* __restrict__ b_a, AttnSh* s)
{
    const int tid = threadIdx.x, lane = tid & 31, w = tid >> 5;
    // reduce hp partials + bias
    for (int j = tid; j < 512; j += 256) {
        float v = b_a[j];
#pragma unroll
        for (int kz = 0; kz < 8; kz++)
            v += __ldcg(d_hppart + kz * B_ * H_ + b * 512 + j);
        s->hp[j] = v;
    }
    __syncthreads();

    const int s0 = lowbound(batch_idx, NN_, b);
    const int s1 = lowbound(batch_idx, NN_, b + 1);

    float m = -INFINITY, ssum = 0.f;
    float ctx[16];
#pragma unroll
    for (int i = 0; i < 16; i++) ctx[i] = 0.f;

    for (int n = s0 + w; n < s1; n += 8) {
        const float* np = d_node_proj + (size_t)n * 512;
        float v[16]; float p = 0.f;
#pragma unroll
        for (int i = 0; i < 16; i++) {
            v[i] = np[lane + 32 * i];
            p = fmaf(v[i], s->hp[lane + 32 * i], p);
        }
#pragma unroll
        for (int o = 16; o > 0; o >>= 1) p += __shfl_xor_sync(0xffffffffu, p, o);
        float mn = fmaxf(m, p);
        float scale = expf(m - mn);
        float e = expf(p - mn);
        ssum = ssum * scale + e;
#pragma unroll
        for (int i = 0; i < 16; i++) ctx[i] = ctx[i] * scale + e * v[i];
        m = mn;
    }
#pragma unroll
    for (int i = 0; i < 16; i++) s->ctx[w][lane + 32 * i] = ctx[i];
    if (lane == 0) { s->m[w] = m; s->s[w] = ssum; }
    __syncthreads();

    float M = -INFINITY;
#pragma unroll
    for (int ww = 0; ww < 8; ww++) M = fmaxf(M, s->m[ww]);
    if (M == -INFINITY) {
        for (int j = tid; j < 512; j += 256) {
            __nv_bfloat16 hh, hl; split1(0.f, hh, hl);
            d_xah[b * 1024 + j] = hh; d_xal[b * 1024 + j] = hl;
        }
    } else {
        float stot = 0.f;
        float ew[8];
#pragma unroll
        for (int ww = 0; ww < 8; ww++) { ew[ww] = expf(s->m[ww] - M); stot += s->s[ww] * ew[ww]; }
        float inv = 1.f / stot;
        for (int j = tid; j < 512; j += 256) {
            float num = 0.f;
#pragma unroll
            for (int ww = 0; ww < 8; ww++) num = fmaf(s->ctx[ww][j], ew[ww], num);
            float v = num * inv;
            __nv_bfloat16 hh, hl; split1(v, hh, hl);
            d_xah[b * 1024 + j] = hh; d_xal[b * 1024 + j] = hl;
        }
    }
}

__device__ __forceinline__ void cell0_phase(int i, int t)
{
    int b = i >> 9, j = i & 511;
    const float* ep = d_embpart + (size_t)t * B_ * G4 + b * G4 + j;
    float g[4];
#pragma unroll
    for (int q = 0; q < 4; q++) {
        float v = ep[q * 512];
#pragma unroll
        for (int kz = 0; kz < 4; kz++)
            v += __ldcg(d_gpart0 + kz * B_ * G4 + b * G4 + q * 512 + j);
        g[q] = v;
    }
    float c = sigf(g[1]) * d_c0[i] + sigf(g[0]) * tanhf(g[2]);
    float h = sigf(g[3]) * tanhf(c);
    d_c0[i] = c;
    __nv_bfloat16 hh, hl; split1(h, hh, hl);
    d_xah[b * 1024 + 512 + j] = hh; d_xal[b * 1024 + 512 + j] = hl;
    d_xbh[b * 1024 + j] = hh;       d_xbl[b * 1024 + j] = hl;
}

__device__ __forceinline__ void cell1_phase(int i, int t)
{
    int b = i >> 9, j = i & 511;
    float g[4];
#pragma unroll
    for (int q = 0; q < 4; q++) {
        float v = d_bs1[q * 512 + j];
#pragma unroll
        for (int kz = 0; kz < 4; kz++)
            v += __ldcg(d_gpart1 + kz * B_ * G4 + b * G4 + q * 512 + j);
        g[q] = v;
    }
    float c = sigf(g[1]) * d_c1[i] + sigf(g[0]) * tanhf(g[2]);
    float h = sigf(g[3]) * tanhf(c);
    d_c1[i] = c;
    __nv_bfloat16 hh, hl; split1(h, hh, hl);
    d_xbh[b * 1024 + 512 + j] = hh; d_xbl[b * 1024 + 512 + j] = hl;
    d_hist[((size_t)b * T_ + t) * H_ + j] = h;
}

__global__ __launch_bounds__(256) void recur_kernel(
    const int* __restrict__ batch_idx, const float* __restrict__ b_a)
{
    __shared__ __align__(16) RecSh sh;
    const int blk = blockIdx.x;
    const int tid = threadIdx.x;
    unsigned bar = 0;

    for (int t = 0; t < T_; t++) {
        // P1: hp partials: 64 tasks (8 n-tiles x 8 k-chunks of 64)
        if (blk < 64) {
            int n0 = (blk & 7) * 64, kz = blk >> 3;
            gemm64_hmma(d_xbh + 512, d_xbl + 512, 1024, kz * 64, 64,
                        d_Wah, d_Wal, 512, n0,
                        d_hppart + kz * B_ * H_, 512, sh.g);
        }
        gbar(bar);
        // P2: attention (adds b_a + hp partial reduce)
        if (blk < 64) attn_phase(blk, batch_idx, b_a, &sh.a);
        gbar(bar);
        // P3: gates0 partials: 128 tasks (32 n-tiles x 4 k-chunks of 256)
        if (blk < 128) {
            int n0 = (blk & 31) * 64, kz = blk >> 5;
            gemm64_hmma(d_xah, d_xal, 1024, kz * 256, 256,
                        d_W0h, d_W0l, 1024, n0,
                        d_gpart0 + kz * B_ * G4, G4, sh.g);
        }
        gbar(bar);
        // P4: cell0
        if (blk < 128) cell0_phase(blk * 256 + tid, t);
        gbar(bar);
        // P5: gates1 partials
        if (blk < 128) {
            int n0 = (blk & 31) * 64, kz = blk >> 5;
            gemm64_hmma(d_xbh, d_xbl, 1024, kz * 256, 256,
                        d_W1h, d_W1l, 1024, n0,
                        d_gpart1 + kz * B_ * G4, G4, sh.g);
        }
        gbar(bar);
        // P6: cell1
        if (blk < 128) cell1_phase(blk * 256 + tid, t);
        gbar(bar);
    }
}

// ---------------- one-time prep ------------------------------------------
__global__ void prep_kernel(
    const float* __restrict__ gf,
    const float* __restrict__ W_a,
    const float* __restrict__ W_ih0, const float* __restrict__ W_hh0,
    const float* __restrict__ b_ih0, const float* __restrict__ b_hh0,
    const float* __restrict__ W_ih1, const float* __restrict__ W_hh1,
    const float* __restrict__ b_ih1, const float* __restrict__ b_hh1,
    const int* __restrict__ captions)
{
    int i = blockIdx.x * blockDim.x + threadIdx.x;
    if (i < G4 * 1024) {
        int n = i >> 10, k = i & 1023;
        float w0 = (k < 512) ? W_ih0[n * 1024 + 512 + k] : W_hh0[n * 512 + (k - 512)];
        float w1 = (k < 512) ? W_ih1[n * 512 + k] : W_hh1[n * 512 + (k - 512)];
        __nv_bfloat16 h, l;
        split1(w0, h, l); d_W0h[i] = h; d_W0l[i] = l;
        split1(w1, h, l); d_W1h[i] = h; d_W1l[i] = l;
    }
    if (i < H_ * H_) {
        __nv_bfloat16 h, l;
        split1(W_a[i], h, l); d_Wah[i] = h; d_Wal[i] = l;
    }
    if (i < G4) { d_bs0[i] = b_ih0[i] + b_hh0[i]; d_bs1[i] = b_ih1[i] + b_hh1[i]; }
    if (i < T_ * B_) { int t = i / 64, b = i % 64; d_gidx[i] = captions[b * T_ + t]; }
    if (i < B_ * H_) {
        int b = i >> 9, j = i & 511;
        __nv_bfloat16 h, l;
        split1(gf[i], h, l);
        d_xah[b * 1024 + 512 + j] = h; d_xal[b * 1024 + 512 + j] = l;  // h0
        d_xbh[b * 1024 + 512 + j] = h; d_xbl[b * 1024 + 512 + j] = l;  // h1
        d_c0[i] = 0.f;
        d_c1[i] = 0.f;
    }
    if (i == 0) g_cnt = 0u;
}

// ---------------- launch --------------------------------------------------
extern "C" void kernel_launch(void* const* d_in, const int* in_sizes, int n_in,
                              void* d_out, int out_size)
{
    const float* gf     = (const float*)d_in[0];
    const float* nf     = (const float*)d_in[1];
    const float* emb    = (const float*)d_in[2];
    const float* W_a    = (const float*)d_in[3];
    const float* b_a    = (const float*)d_in[4];
    const float* W_c    = (const float*)d_in[5];
    const float* b_c    = (const float*)d_in[6];
    const float* W_ih0  = (const float*)d_in[7];
    const float* W_hh0  = (const float*)d_in[8];
    const float* b_ih0  = (const float*)d_in[9];
    const float* b_hh0  = (const float*)d_in[10];
    const float* W_ih1  = (const float*)d_in[11];
    const float* W_hh1  = (const float*)d_in[12];
    const float* b_ih1  = (const float*)d_in[13];
    const float* b_hh1  = (const float*)d_in[14];
    const float* W_fc   = (const float*)d_in[15];
    const float* b_fc   = (const float*)d_in[16];
    const int* batch_idx = (const int*)d_in[17];
    const int* captions  = (const int*)d_in[18];
    float* out = (float*)d_out;

    float *node_proj, *embpart, *hist, *bs0;
    int* gidx;
    cudaGetSymbolAddress((void**)&node_proj, d_node_proj);
    cudaGetSymbolAddress((void**)&embpart,   d_embpart);
    cudaGetSymbolAddress((void**)&hist,      d_hist);
    cudaGetSymbolAddress((void**)&bs0,       d_bs0);
    cudaGetSymbolAddress((void**)&gidx,      d_gidx);

    cudaFuncSetAttribute(tgemm, cudaFuncAttributeMaxDynamicSharedMemorySize, TG_SMEM);

    // one-time prep: weight splits, bias sums, gather indices, state init
    prep_kernel<<<8192, 256>>>(gf, W_a, W_ih0, W_hh0, b_ih0, b_hh0,
                               W_ih1, W_hh1, b_ih1, b_hh1, captions);

    // node_proj = node_features @ W_c^T + b_c         [8192, 512]
    tgemm<<<dim3(NN_ / 128, H_ / 128), 256, TG_SMEM>>>(
        nf, H_, W_c, H_, node_proj, H_, b_c, H_, nullptr);

    // embpart = emb[captions] @ W_ih0[:, :512]^T + (b_ih0+b_hh0)   [1280, 2048]
    tgemm<<<dim3(T_ * B_ / 128, G4 / 128), 256, TG_SMEM>>>(
        emb, E_, W_ih0, 1024, embpart, G4, bs0, E_, gidx);

    // full recurrence: ONE persistent kernel, 20 steps, global barriers
    recur_kernel<<<NB, 256>>>(batch_idx, b_a);

    // logits = hist @ W_fc^T + b_fc  -> directly into out[b][t][v]
    tgemm<<<dim3(B_ * T_ / 128, V_ / 128), 256, TG_SMEM>>>(
        hist, H_, W_fc, H_, out, V_, b_fc, H_, nullptr);
}